// round 13
// baseline (speedup 1.0000x reference)
#include <cuda_runtime.h>
#include <cstdint>

#define BB    64
#define HH    1024
#define SS    512
#define NP    16          // row-pairs per lane: rows (l+64j, l+64j+32)
#define TC    16          // t-steps per staged chunk
#define NCHUNK (SS / TC)  // 32
#define ROWB  80          // 64 B data (16 t-floats) + 16 B pad
#define STAGE_BYTES (HH * ROWB)            // 81920
#define MASK_OFF    (2 * STAGE_BYTES)
#define SMEM_TOTAL  (MASK_OFF + (SS + 8) * 4)

typedef unsigned long long u64;

// ---- packed f32x2 (sm_103a: fma/mul/add only) ----
__device__ __forceinline__ u64 pack2(float lo, float hi) {
    u64 r; asm("mov.b64 %0, {%1, %2};" : "=l"(r) : "f"(lo), "f"(hi)); return r;
}
__device__ __forceinline__ void unpack2(u64 v, float& lo, float& hi) {
    asm("mov.b64 {%0, %1}, %2;" : "=f"(lo), "=f"(hi) : "l"(v));
}
__device__ __forceinline__ u64 fma2(u64 a, u64 b, u64 c) {
    u64 d; asm("fma.rn.f32x2 %0, %1, %2, %3;" : "=l"(d) : "l"(a), "l"(b), "l"(c)); return d;
}
__device__ __forceinline__ u64 mul2(u64 a, u64 b) {
    u64 d; asm("mul.rn.f32x2 %0, %1, %2;" : "=l"(d) : "l"(a), "l"(b)); return d;
}
__device__ __forceinline__ u64 add2(u64 a, u64 b) {
    u64 d; asm("add.rn.f32x2 %0, %1, %2;" : "=l"(d) : "l"(a), "l"(b)); return d;
}
__device__ __forceinline__ u64 clip2(u64 v) {   // FMNMX on alu pipe; movs fold away
    float lo, hi; unpack2(v, lo, hi);
    lo = fminf(1.0f, fmaxf(-1.0f, lo));
    hi = fminf(1.0f, fmaxf(-1.0f, hi));
    return pack2(lo, hi);
}
__device__ __forceinline__ float hsum4(u64 a, u64 b, u64 c, u64 d) {
    u64 e = add2(add2(a, b), add2(c, d));
    float lo, hi; unpack2(e, lo, hi); return lo + hi;
}

__device__ __forceinline__ float shfl_bfly(float v, int ofs) {
    unsigned r;
    asm volatile("shfl.sync.bfly.b32 %0, %1, %2, 0x1f, 0xffffffff;"
                 : "=r"(r) : "r"(__float_as_uint(v)), "r"(ofs));
    return __uint_as_float(r);
}
// Full warp reduction == full H reduction. No smem, no barrier.
__device__ __forceinline__ void wred3(float& a, float& b, float& c) {
    #pragma unroll
    for (int ofs = 16; ofs > 0; ofs >>= 1) {
        a += shfl_bfly(a, ofs);
        b += shfl_bfly(b, ofs);
        c += shfl_bfly(c, ofs);
    }
}

__device__ __forceinline__ void cp16(uint32_t smem_dst, const void* gmem_src) {
    asm volatile("cp.async.cg.shared.global [%0], [%1], 16;"
                 :: "r"(smem_dst), "l"(gmem_src));
}

// Stage 2 of 16 row-pieces (16 cp16, warp-wide) of `chunk`. s in [0,8).
__device__ __forceinline__ void stage2(char* smem, const char* seq_b,
                                       int chunk, int s, int l) {
    char* dst = smem + (chunk & 1) * STAGE_BYTES;
    const char* src = seq_b + (size_t)chunk * (TC * 4);
    #pragma unroll
    for (int i = 0; i < 16; i++) {
        int idx = s * 512 + i * 32 + l;           // 16B-block id: (row, p)
        int row = idx >> 2, p = idx & 3;
        uint32_t d = (uint32_t)__cvta_generic_to_shared(dst + row * ROWB + p * 16);
        cp16(d, src + (size_t)row * (SS * 4) + p * 16);
    }
    asm volatile("cp.async.commit_group;");
}

__global__ void __launch_bounds__(32, 1)
orth_scan_kernel(const float* __restrict__ tree,
                 const float* __restrict__ seq,
                 const float* __restrict__ mask,
                 float* __restrict__ out)
{
    extern __shared__ char sm[];
    const int l = threadIdx.x;
    const int b = blockIdx.x;
    const char* seq_b = (const char*)(seq + (size_t)b * HH * SS);
    float* msk = (float*)(sm + MASK_OFF);

    for (int i = l; i < SS; i += 32) msk[i] = mask[b * SS + i];
    if (l < 8) msk[SS + l] = 0.f;     // prefetch guards

    u64 h2[NP];
    #pragma unroll
    for (int j = 0; j < NP; j++)
        h2[j] = pack2(tree[b * HH + l + 64 * j], tree[b * HH + l + 64 * j + 32]);

    // Prologue: stage chunk 0 fully (single-warp: wait + syncwarp suffices).
    #pragma unroll
    for (int s = 0; s < 8; s++) stage2(sm, seq_b, 0, s, l);
    asm volatile("cp.async.wait_group 0;");
    __syncwarp();

    float pdot, phh, pss;
    float mcur = msk[0], mnext = msk[1];
    u64 bs2[NP];
    {
        u64 d0 = 0, d1 = 0, q0 = 0, q1 = 0, w0 = 0, w1 = 0;
        const u64 m2 = pack2(mcur, mcur);
        #pragma unroll
        for (int j = 0; j < NP; j++) {
            float lo = *(const float*)(sm + (l + 64 * j) * ROWB);
            float hi = *(const float*)(sm + (l + 64 * j + 32) * ROWB);
            u64 s2 = pack2(lo, hi);
            bs2[j] = mul2(m2, s2);
            if (j & 1) { d1 = fma2(h2[j], s2, d1); q1 = fma2(h2[j], h2[j], q1); w1 = fma2(s2, s2, w1); }
            else       { d0 = fma2(h2[j], s2, d0); q0 = fma2(h2[j], h2[j], q0); w0 = fma2(s2, s2, w0); }
        }
        pdot = hsum4(d0, d1, 0, 0);
        phh  = hsum4(q0, q1, 0, 0);
        pss  = hsum4(w0, w1, 0, 0);
    }

    #pragma unroll 2
    for (int t = 0; t < SS; t++) {
        // 1. Warp tree: the ENTIRE reduction (no cross-warp stage exists).
        wred3(pdot, phh, pss);

        const int tn = t + 1;
        // 2. Chunk boundary: staged >=8 steps ago; wait is ~free.
        if ((tn & 15) == 0) {
            asm volatile("cp.async.wait_group 0;");
            __syncwarp();
        }

        // 3. Shadow work under tree latency: s_{t+1} loads, pssn, bsn, mask.
        const char* sb = sm + ((tn >> 4) & 1) * STAGE_BYTES + (tn & 15) * 4;
        float snlo[NP], snhi[NP];
        #pragma unroll
        for (int j = 0; j < NP; j++) {
            snlo[j] = *(const float*)(sb + (l + 64 * j) * ROWB);
            snhi[j] = *(const float*)(sb + (l + 64 * j + 32) * ROWB);
        }
        const float mnn = msk[t + 2];
        const u64 m2n = pack2(mnext, mnext);
        u64 snN[NP], bsn[NP];
        u64 w0 = 0, w1 = 0, w2 = 0, w3 = 0;
        #pragma unroll
        for (int j = 0; j < NP; j++) {
            snN[j] = pack2(snlo[j], snhi[j]);
            bsn[j] = mul2(m2n, snN[j]);
            switch (j & 3) {
                case 0: w0 = fma2(snN[j], snN[j], w0); break;
                case 1: w1 = fma2(snN[j], snN[j], w1); break;
                case 2: w2 = fma2(snN[j], snN[j], w2); break;
                default: w3 = fma2(snN[j], snN[j], w3); break;
            }
        }
        const float pssn = hsum4(w0, w1, w2, w3);

        // 4. Staging: 2 pieces/step on local steps 0..7 -> chunk done 8 steps early.
        const int tl = t & 15;
        if (tl < 8 && t < SS - TC)
            stage2(sm, seq_b, (t >> 4) + 1, tl, l);

        // 5. cos (tree results) -> alpha -> update + fused next partials.
        const float cosv  = pdot * rsqrtf(fmaxf(phh * pss, 1e-16f));
        const float alpha = fmaf(-mcur, cosv, 1.0f);   // h_new = clip(alpha*h + m*s)
        const u64 a2 = pack2(alpha, alpha);

        u64 pd0 = 0, pd1 = 0, pd2 = 0, pd3 = 0;
        u64 ph0 = 0, ph1 = 0, ph2 = 0, ph3 = 0;
        #pragma unroll
        for (int j = 0; j < NP; j++) {
            u64 hn = clip2(fma2(a2, h2[j], bs2[j]));
            switch (j & 3) {
                case 0: pd0 = fma2(hn, snN[j], pd0); ph0 = fma2(hn, hn, ph0); break;
                case 1: pd1 = fma2(hn, snN[j], pd1); ph1 = fma2(hn, hn, ph1); break;
                case 2: pd2 = fma2(hn, snN[j], pd2); ph2 = fma2(hn, hn, ph2); break;
                default: pd3 = fma2(hn, snN[j], pd3); ph3 = fma2(hn, hn, ph3); break;
            }
            h2[j]  = hn;
            bs2[j] = bsn[j];
        }
        pdot = hsum4(pd0, pd1, pd2, pd3);
        phh  = hsum4(ph0, ph1, ph2, ph3);
        pss  = pssn;
        mcur = mnext; mnext = mnn;
    }

    #pragma unroll
    for (int j = 0; j < NP; j++) {
        float lo, hi; unpack2(h2[j], lo, hi);
        out[b * HH + l + 64 * j]      = lo;
        out[b * HH + l + 64 * j + 32] = hi;
    }
}

extern "C" void kernel_launch(void* const* d_in, const int* in_sizes, int n_in,
                              void* d_out, int out_size)
{
    const float* tree = (const float*)d_in[0];  // (B, H)
    const float* seq  = (const float*)d_in[1];  // (B, H, S)
    const float* mask = (const float*)d_in[2];  // (B, S)
    float* out = (float*)d_out;                 // (B, H)

    cudaFuncSetAttribute(orth_scan_kernel,
                         cudaFuncAttributeMaxDynamicSharedMemorySize, SMEM_TOTAL);
    orth_scan_kernel<<<BB, 32, SMEM_TOTAL>>>(tree, seq, mask, out);
}

// round 14
// speedup vs baseline: 1.7319x; 1.7319x over previous
#include <cuda.h>
#include <cuda_runtime.h>
#include <cstdint>

#define BB    64
#define HH    1024
#define SS    512
#define NTHR  128
#define NW    4
#define KK    8           // rows per thread
#define NP    4           // packed row-pairs per thread
#define TC    16          // t-steps per chunk
#define NCHUNK (SS / TC)  // 32
#define BUFB  65536       // one chunk: 1024 rows * 64 B (SW64-swizzled by TMA)
#define NBUF  3
#define MASK_OFF    (NBUF * BUFB)               // 196608
#define MBAR_OFF    (MASK_OFF + (SS + 8) * 4)   // 198688 (8B aligned)
#define RED_OFF     (MBAR_OFF + 32)
#define SMEM_TOTAL  (RED_OFF + 2 * NW * 16)

typedef unsigned long long u64;

// ---- packed f32x2 (sm_103a: fma/mul/add only) ----
__device__ __forceinline__ u64 pack2(float lo, float hi) {
    u64 r; asm("mov.b64 %0, {%1, %2};" : "=l"(r) : "f"(lo), "f"(hi)); return r;
}
__device__ __forceinline__ void unpack2(u64 v, float& lo, float& hi) {
    asm("mov.b64 {%0, %1}, %2;" : "=f"(lo), "=f"(hi) : "l"(v));
}
__device__ __forceinline__ u64 fma2(u64 a, u64 b, u64 c) {
    u64 d; asm("fma.rn.f32x2 %0, %1, %2, %3;" : "=l"(d) : "l"(a), "l"(b), "l"(c)); return d;
}
__device__ __forceinline__ u64 mul2(u64 a, u64 b) {
    u64 d; asm("mul.rn.f32x2 %0, %1, %2;" : "=l"(d) : "l"(a), "l"(b)); return d;
}
__device__ __forceinline__ u64 add2(u64 a, u64 b) {
    u64 d; asm("add.rn.f32x2 %0, %1, %2;" : "=l"(d) : "l"(a), "l"(b)); return d;
}
__device__ __forceinline__ u64 clip2(u64 v) {
    float lo, hi; unpack2(v, lo, hi);
    lo = fminf(1.0f, fmaxf(-1.0f, lo));
    hi = fminf(1.0f, fmaxf(-1.0f, hi));
    return pack2(lo, hi);
}
__device__ __forceinline__ float hsum2_2(u64 a, u64 b) {
    u64 e = add2(a, b);
    float lo, hi; unpack2(e, lo, hi); return lo + hi;
}

__device__ __forceinline__ float shfl_bfly(float v, int ofs) {
    unsigned r;
    asm volatile("shfl.sync.bfly.b32 %0, %1, %2, 0x1f, 0xffffffff;"
                 : "=r"(r) : "r"(__float_as_uint(v)), "r"(ofs));
    return __uint_as_float(r);
}
__device__ __forceinline__ void wred3(float& a, float& b, float& c) {
    #pragma unroll
    for (int ofs = 16; ofs > 0; ofs >>= 1) {
        a += shfl_bfly(a, ofs);
        b += shfl_bfly(b, ofs);
        c += shfl_bfly(c, ofs);
    }
}

// ---- TMA / mbarrier ----
__device__ __forceinline__ void mbar_init(uint32_t mbar, uint32_t cnt) {
    asm volatile("mbarrier.init.shared.b64 [%0], %1;" :: "r"(mbar), "r"(cnt) : "memory");
}
__device__ __forceinline__ void mbar_expect(uint32_t mbar, uint32_t bytes) {
    asm volatile("mbarrier.arrive.expect_tx.shared.b64 _, [%0], %1;"
                 :: "r"(mbar), "r"(bytes) : "memory");
}
__device__ __forceinline__ void mbar_wait(uint32_t mbar, uint32_t parity) {
    asm volatile(
        "{\n\t.reg .pred P;\n\t"
        "WL_%=:\n\t"
        "mbarrier.try_wait.parity.acquire.cta.shared::cta.b64 P, [%0], %1, 0x989680;\n\t"
        "@P bra WD_%=;\n\t"
        "bra WL_%=;\n\t"
        "WD_%=:\n\t}"
        :: "r"(mbar), "r"(parity) : "memory");
}
__device__ __forceinline__ void tma2d(uint32_t dst, const CUtensorMap* map,
                                      int cx, int cy, uint32_t mbar) {
    asm volatile(
        "cp.async.bulk.tensor.2d.shared::cta.global.tile.mbarrier::complete_tx::bytes "
        "[%0], [%1, {%2, %3}], [%4];"
        :: "r"(dst), "l"(map), "r"(cx), "r"(cy), "r"(mbar) : "memory");
}
// Issue one chunk: expect 64KB + 4 boxes of 16x256 floats.
__device__ __forceinline__ void issue_chunk(uint32_t smbase, const CUtensorMap* map,
                                            int chunk, int b, uint32_t mbar_base) {
    uint32_t mb  = mbar_base + (chunk % NBUF) * 8;
    uint32_t dst = smbase + (chunk % NBUF) * BUFB;
    mbar_expect(mb, BUFB);
    #pragma unroll
    for (int i = 0; i < 4; i++)
        tma2d(dst + i * 16384, map, chunk * TC, b * HH + i * 256, mb);
}

__global__ void __launch_bounds__(NTHR, 1)
orth_scan_kernel(const __grid_constant__ CUtensorMap tmap,
                 const float* __restrict__ tree,
                 const float* __restrict__ mask,
                 float* __restrict__ out)
{
    extern __shared__ char sm[];
    const int b    = blockIdx.x;
    const int tid  = threadIdx.x;
    const int wid  = tid >> 5;
    const int lane = tid & 31;
    const uint32_t smbase = (uint32_t)__cvta_generic_to_shared(sm);
    const uint32_t mbarb  = smbase + MBAR_OFF;

    float* msk = (float*)(sm + MASK_OFF);
    float* red = (float*)(sm + RED_OFF);

    #pragma unroll
    for (int i = tid; i < SS; i += NTHR) msk[i] = mask[b * SS + i];
    if (tid < 8) msk[SS + tid] = 0.f;

    // mbarriers + first 3 chunks via TMA
    if (tid == 0) {
        #pragma unroll
        for (int i = 0; i < NBUF; i++) mbar_init(mbarb + i * 8, 1);
        asm volatile("fence.proxy.async.shared::cta;" ::: "memory");
        issue_chunk(smbase, &tmap, 0, b, mbarb);
        issue_chunk(smbase, &tmap, 1, b, mbarb);
        issue_chunk(smbase, &tmap, 2, b, mbarb);
    }

    // Carried state (packed pairs: rows tid+2j*128, tid+(2j+1)*128)
    u64 h2[NP], scur2[NP];
    {
        float hv[KK];
        #pragma unroll
        for (int k = 0; k < KK; k++) hv[k] = tree[b * HH + tid + k * NTHR];
        #pragma unroll
        for (int j = 0; j < NP; j++) h2[j] = pack2(hv[2 * j], hv[2 * j + 1]);
    }

    // Swizzled per-row smem offsets: row r -> r*64 | (((r>>1)&3)*16); col-group c: ^ c*16
    uint32_t koff[KK];
    #pragma unroll
    for (int k = 0; k < KK; k++) {
        uint32_t r = tid + k * NTHR;
        koff[k] = r * 64 + (((r >> 1) & 3) * 16);
    }

    __syncthreads();                 // mbar init visible
    mbar_wait(mbarb + 0, 0);         // chunk 0 landed

    float4 s4[KK];
    float pdot, phh, pss;
    {
        #pragma unroll
        for (int k = 0; k < KK; k++)
            s4[k] = *(const float4*)(sm + koff[k]);   // buffer 0, col-group 0
        #pragma unroll
        for (int j = 0; j < NP; j++) scur2[j] = pack2(s4[2 * j].x, s4[2 * j + 1].x);
        u64 d0 = 0, d1 = 0, q0 = 0, q1 = 0, w0 = 0, w1 = 0;
        #pragma unroll
        for (int j = 0; j < NP; j++) {
            u64* dd = (j & 1) ? &d1 : &d0;
            u64* qq = (j & 1) ? &q1 : &q0;
            u64* ww = (j & 1) ? &w1 : &w0;
            *dd = fma2(h2[j], scur2[j], *dd);
            *qq = fma2(h2[j], h2[j], *qq);
            *ww = fma2(scur2[j], scur2[j], *ww);
        }
        pdot = hsum2_2(d0, d1); phh = hsum2_2(q0, q1); pss = hsum2_2(w0, w1);
    }
    float mcur = msk[0];

    for (int c = 0; c < NCHUNK; c++) {
        char* bufc = sm + (c % NBUF) * BUFB;
        char* bufn = sm + ((c + 1) % NBUF) * BUFB;
        const uint32_t parn = (uint32_t)(((c + 1) / NBUF) & 1);
        const bool wait_next  = (c + 1) < NCHUNK;
        const bool issue_more = (c + 3) < NCHUNK + 0 && (c + 3) <= NCHUNK - 1;

        #pragma unroll
        for (int tl = 0; tl < TC; tl++) {
            const int t    = c * TC + tl;
            const int par  = tl & 1;
            const int comp = (tl + 1) & 3;

            // 1. 5-level warp tree (15 SHFL), first.
            wred3(pdot, phh, pss);

            // 2. Publish per-warp partials.
            if (lane == 0) {
                float4* rp = (float4*)(red + par * (NW * 4)) + wid;
                *rp = make_float4(pdot, phh, pss, 0.f);
            }

            // 3. Pre-barrier cos-independent work.
            const float m = mcur;
            mcur = msk[t + 1];
            const u64 m2 = pack2(m, m);

            u64 bs2[NP];
            #pragma unroll
            for (int j = 0; j < NP; j++) bs2[j] = mul2(m2, scur2[j]);

            u64 sn2[NP];
            float pssn = 0.f;
            if (tl != TC - 1) {
                if ((tl & 3) == 3) {
                    const uint32_t c16 = (uint32_t)(((tl + 1) >> 2) * 16);
                    #pragma unroll
                    for (int k = 0; k < KK; k++)
                        s4[k] = *(const float4*)(bufc + (koff[k] ^ c16));
                }
                #pragma unroll
                for (int j = 0; j < NP; j++) {
                    float a = (comp == 0) ? s4[2*j].x : (comp == 1) ? s4[2*j].y
                            : (comp == 2) ? s4[2*j].z : s4[2*j].w;
                    float bb = (comp == 0) ? s4[2*j+1].x : (comp == 1) ? s4[2*j+1].y
                             : (comp == 2) ? s4[2*j+1].z : s4[2*j+1].w;
                    sn2[j] = pack2(a, bb);
                }
                u64 w0 = 0, w1 = 0;
                #pragma unroll
                for (int j = 0; j < NP; j++) {
                    if (j & 1) w1 = fma2(sn2[j], sn2[j], w1);
                    else       w0 = fma2(sn2[j], sn2[j], w0);
                }
                pssn = hsum2_2(w0, w1);
            }

            __syncthreads();

            // 4. Post-barrier: chain-critical combine loads first.
            const float4* rp = (const float4*)(red + par * (NW * 4));
            float4 v0 = rp[0], v1 = rp[1], v2 = rp[2], v3 = rp[3];

            if (tl == TC - 1) {
                if (wait_next) mbar_wait(mbarb + ((c + 1) % NBUF) * 8, parn);
                #pragma unroll
                for (int k = 0; k < KK; k++)
                    s4[k] = *(const float4*)(bufn + koff[k]);   // next chunk, col-group 0
                // at c==NCHUNK-1 these are stale-but-in-bounds; results discarded
                #pragma unroll
                for (int j = 0; j < NP; j++) {
                    float a = (comp == 0) ? s4[2*j].x : (comp == 1) ? s4[2*j].y
                            : (comp == 2) ? s4[2*j].z : s4[2*j].w;
                    float bb = (comp == 0) ? s4[2*j+1].x : (comp == 1) ? s4[2*j+1].y
                             : (comp == 2) ? s4[2*j+1].z : s4[2*j+1].w;
                    sn2[j] = pack2(a, bb);
                }
                u64 w0 = 0, w1 = 0;
                #pragma unroll
                for (int j = 0; j < NP; j++) {
                    if (j & 1) w1 = fma2(sn2[j], sn2[j], w1);
                    else       w0 = fma2(sn2[j], sn2[j], w0);
                }
                pssn = hsum2_2(w0, w1);
            }

            // TMA for chunk c+3 into this chunk's buffer (dead after tl==11's reads).
            if (tl == 12 && tid == 0 && issue_more)
                issue_chunk(smbase, &tmap, c + 3, b, mbarb);

            float dot = (v0.x + v1.x) + (v2.x + v3.x);
            float hh  = (v0.y + v1.y) + (v2.y + v3.y);
            float ss  = (v0.z + v1.z) + (v2.z + v3.z);

            // cos = dot / max(||h||*||s||, 1e-8) == dot * rsqrt(max(hh*ss, 1e-16))
            const float cosv = dot * rsqrtf(fmaxf(hh * ss, 1e-16f));
            const float alpha = fmaf(-m, cosv, 1.0f);   // h_new = clip(alpha*h + m*s)
            const u64 a2 = pack2(alpha, alpha);

            u64 pd0 = 0, pd1 = 0, ph0 = 0, ph1 = 0;
            #pragma unroll
            for (int j = 0; j < NP; j++) {
                u64 hn = clip2(fma2(a2, h2[j], bs2[j]));
                if (j & 1) { pd1 = fma2(hn, sn2[j], pd1); ph1 = fma2(hn, hn, ph1); }
                else       { pd0 = fma2(hn, sn2[j], pd0); ph0 = fma2(hn, hn, ph0); }
                h2[j]    = hn;
                scur2[j] = sn2[j];
            }
            pdot = hsum2_2(pd0, pd1);
            phh  = hsum2_2(ph0, ph1);
            pss  = pssn;
        }
    }

    #pragma unroll
    for (int j = 0; j < NP; j++) {
        float lo, hi; unpack2(h2[j], lo, hi);
        out[b * HH + tid + (2 * j) * NTHR]     = lo;
        out[b * HH + tid + (2 * j + 1) * NTHR] = hi;
    }
}

typedef CUresult (*EncodeFn)(CUtensorMap*, CUtensorMapDataType, cuuint32_t, void*,
                             const cuuint64_t*, const cuuint64_t*, const cuuint32_t*,
                             const cuuint32_t*, CUtensorMapInterleave, CUtensorMapSwizzle,
                             CUtensorMapL2promotion, CUtensorMapFloatOOBfill);

extern "C" void kernel_launch(void* const* d_in, const int* in_sizes, int n_in,
                              void* d_out, int out_size)
{
    const float* tree = (const float*)d_in[0];  // (B, H)
    void*        seq  = (void*)d_in[1];         // (B, H, S) fp32
    const float* mask = (const float*)d_in[2];  // (B, S)
    float* out = (float*)d_out;                 // (B, H)

    EncodeFn enc = nullptr;
    cudaGetDriverEntryPointByVersion("cuTensorMapEncodeTiled", (void**)&enc,
                                     12000, cudaEnableDefault, nullptr);

    CUtensorMap tmap;
    cuuint64_t gdim[2] = {SS, (cuuint64_t)BB * HH};       // x = t (contig), y = rows
    cuuint64_t gstr[1] = {SS * 4};                        // row pitch bytes
    cuuint32_t box[2]  = {TC, 256};                       // 16 floats x 256 rows
    cuuint32_t estr[2] = {1, 1};
    enc(&tmap, CU_TENSOR_MAP_DATA_TYPE_FLOAT32, 2, seq, gdim, gstr, box, estr,
        CU_TENSOR_MAP_INTERLEAVE_NONE, CU_TENSOR_MAP_SWIZZLE_64B,
        CU_TENSOR_MAP_L2_PROMOTION_L2_128B, CU_TENSOR_MAP_FLOAT_OOB_FILL_NONE);

    cudaFuncSetAttribute(orth_scan_kernel,
                         cudaFuncAttributeMaxDynamicSharedMemorySize, SMEM_TOTAL);
    orth_scan_kernel<<<BB, NTHR, SMEM_TOTAL>>>(tmap, tree, mask, out);
}